// round 13
// baseline (speedup 1.0000x reference)
#include <cuda_runtime.h>
#include <cstdint>
#include <cstddef>

#define BB 128
#define TT 512
#define DD 256
#define HH 512
#define GG 2048  // 4*H

// ---- device scratch (static globals: sanctioned no-alloc workaround) ----
__device__ float g_M[GG * DD];                 // permuted (wx0 @ proj_w)
__device__ float g_bias0[GG];                  // permuted wx0@proj_b + bx0 + bh0
__device__ float g_xg[(size_t)TT * BB * GG];   // x-gates, [t][b][jp] permuted
__device__ float g_h0[2][BB * HH];
__device__ float g_c0[BB * HH];
__device__ float g_h1[2][BB * HH];
__device__ float g_c1[BB * HH];

__device__ __forceinline__ float sigf(float x) { return 1.0f / (1.0f + __expf(-x)); }

// jo = (jp&3)*H + (jp>>2): row jp is gate quad (i,f,g,o) of hidden unit jp>>2
__global__ void prep_M_kernel(const float* __restrict__ wx0,
                              const float* __restrict__ proj_w,
                              const float* __restrict__ proj_b,
                              const float* __restrict__ bx0,
                              const float* __restrict__ bh0)
{
    const int jp = blockIdx.x;
    const int jo = (jp & 3) * HH + (jp >> 2);
    const int e  = threadIdx.x;
    float s = 0.0f;
    for (int d = 0; d < DD; d++) s += wx0[jo * DD + d] * proj_w[d * DD + e];
    g_M[jp * DD + e] = s;
    if (e == 0) {
        float bs = 0.0f;
        for (int d = 0; d < DD; d++) bs += wx0[jo * DD + d] * proj_b[d];
        g_bias0[jp] = bs + bx0[jo] + bh0[jo];
    }
}

__global__ void init_state_kernel()
{
    int i = blockIdx.x * blockDim.x + threadIdx.x;
    if (i < BB * HH) {
        g_h0[0][i] = 0.0f; g_h0[1][i] = 0.0f;
        g_h1[0][i] = 0.0f; g_h1[1][i] = 0.0f;
        g_c0[i] = 0.0f;    g_c1[i] = 0.0f;
    }
}

// xg[r][jp] = x_row(r) . g_M[jp] + g_bias0[jp], rows r = t*128 + b (t-major)
__global__ __launch_bounds__(256) void xg_kernel(const float* __restrict__ x)
{
    __shared__ float As[32][68];
    __shared__ float Bs[32][68];
    const int rb = blockIdx.x >> 5;     // 0..1023
    const int cb = blockIdx.x & 31;     // 0..31
    const int tid = threadIdx.x;
    const int i = tid & 15;             // rows 4i..4i+3
    const int j = tid >> 4;             // cols 4j..4j+3
    const int colbase = cb * 64 + 4 * j;

    float acc[4][4];
#pragma unroll
    for (int q = 0; q < 4; q++) {
        const float bv = g_bias0[colbase + q];
        acc[0][q] = bv; acc[1][q] = bv; acc[2][q] = bv; acc[3][q] = bv;
    }
    for (int kc = 0; kc < DD; kc += 32) {
        __syncthreads();
#pragma unroll
        for (int r = 0; r < 2; r++) {
            const int s = tid + 256 * r;            // 0..511
            const int row = s >> 3, kq = s & 7;
            const int rout = rb * 64 + row;
            const int b = rout & 127, t = rout >> 7;
            const float4 v = *(const float4*)&x[((size_t)(b * TT + t)) * DD + kc + kq * 4];
            As[kq*4+0][row] = v.x; As[kq*4+1][row] = v.y;
            As[kq*4+2][row] = v.z; As[kq*4+3][row] = v.w;
        }
#pragma unroll
        for (int r = 0; r < 2; r++) {
            const int s = tid + 256 * r;
            const int row = s >> 3, kq = s & 7;
            const float4 v = *(const float4*)&g_M[(cb * 64 + row) * DD + kc + kq * 4];
            Bs[kq*4+0][row] = v.x; Bs[kq*4+1][row] = v.y;
            Bs[kq*4+2][row] = v.z; Bs[kq*4+3][row] = v.w;
        }
        __syncthreads();
#pragma unroll
        for (int k = 0; k < 32; k++) {
            const float4 a = *(const float4*)&As[k][4 * i];
            const float4 w = *(const float4*)&Bs[k][4 * j];
            acc[0][0]+=a.x*w.x; acc[0][1]+=a.x*w.y; acc[0][2]+=a.x*w.z; acc[0][3]+=a.x*w.w;
            acc[1][0]+=a.y*w.x; acc[1][1]+=a.y*w.y; acc[1][2]+=a.y*w.z; acc[1][3]+=a.y*w.w;
            acc[2][0]+=a.z*w.x; acc[2][1]+=a.z*w.y; acc[2][2]+=a.z*w.z; acc[2][3]+=a.z*w.w;
            acc[3][0]+=a.w*w.x; acc[3][1]+=a.w*w.y; acc[3][2]+=a.w*w.z; acc[3][3]+=a.w*w.w;
        }
    }
#pragma unroll
    for (int a = 0; a < 4; a++) {
        const int rout = rb * 64 + 4 * i + a;
        float4 v; v.x = acc[a][0]; v.y = acc[a][1]; v.z = acc[a][2]; v.w = acc[a][3];
        *(float4*)&g_xg[(size_t)rout * GG + colbase] = v;
    }
}

// Phase p: blocks 0..63 -> layer0 step p; blocks 64..191 -> layer1 step p-1.
// Both read g_h0[p&1]; layer0 writes g_h0[(p+1)&1]; layer1 writes g_h1[p&1].
__global__ __launch_bounds__(256) void phase_kernel(
    int p,
    const float* __restrict__ wh0,
    const float* __restrict__ wx1, const float* __restrict__ bx1,
    const float* __restrict__ wh1, const float* __restrict__ bh1)
{
    __shared__ float As[32][132];
    __shared__ float Ws[32][36];
    const int bid = blockIdx.x;
    const int tid = threadIdx.x;

    if (bid < 64) {
        if (p >= TT) return;
        const float* __restrict__ A  = g_h0[p & 1];
        const float* __restrict__ xg = g_xg + (size_t)p * BB * GG;
        const int jpb = bid * 32;
        const int i = tid & 31;          // batches 4i..4i+3
        const int j = tid >> 5;          // gate cols 4j..4j+3 (one quad)
        const int col = jpb + 4 * j;

        float acc[4][4];
#pragma unroll
        for (int a = 0; a < 4; a++) {
            const float4 v = *(const float4*)&xg[(size_t)(4 * i + a) * GG + col];
            acc[a][0] = v.x; acc[a][1] = v.y; acc[a][2] = v.z; acc[a][3] = v.w;
        }
        for (int kc = 0; kc < HH; kc += 32) {
            __syncthreads();
#pragma unroll
            for (int r = 0; r < 4; r++) {
                const int s = tid + 256 * r;          // 0..1023
                const int b = s >> 3, kq = s & 7;
                const float4 v = *(const float4*)&A[b * HH + kc + kq * 4];
                As[kq*4+0][b] = v.x; As[kq*4+1][b] = v.y;
                As[kq*4+2][b] = v.z; As[kq*4+3][b] = v.w;
            }
            {
                const int row = tid >> 3, kq = tid & 7;  // 32 rows
                const int jp = jpb + row;
                const int jo = (jp & 3) * HH + (jp >> 2);
                const float4 v = *(const float4*)&wh0[jo * HH + kc + kq * 4];
                Ws[kq*4+0][row] = v.x; Ws[kq*4+1][row] = v.y;
                Ws[kq*4+2][row] = v.z; Ws[kq*4+3][row] = v.w;
            }
            __syncthreads();
#pragma unroll
            for (int k = 0; k < 32; k++) {
                const float4 a = *(const float4*)&As[k][4 * i];
                const float4 w = *(const float4*)&Ws[k][4 * j];
                acc[0][0]+=a.x*w.x; acc[0][1]+=a.x*w.y; acc[0][2]+=a.x*w.z; acc[0][3]+=a.x*w.w;
                acc[1][0]+=a.y*w.x; acc[1][1]+=a.y*w.y; acc[1][2]+=a.y*w.z; acc[1][3]+=a.y*w.w;
                acc[2][0]+=a.z*w.x; acc[2][1]+=a.z*w.y; acc[2][2]+=a.z*w.z; acc[2][3]+=a.z*w.w;
                acc[3][0]+=a.w*w.x; acc[3][1]+=a.w*w.y; acc[3][2]+=a.w*w.z; acc[3][3]+=a.w*w.w;
            }
        }
        const int jh = (jpb >> 2) + j;
        float* __restrict__ hout = g_h0[(p + 1) & 1];
#pragma unroll
        for (int a = 0; a < 4; a++) {
            const int b = 4 * i + a;
            const float ig = sigf(acc[a][0]);
            const float fg = sigf(acc[a][1]);
            const float gg = tanhf(acc[a][2]);
            const float og = sigf(acc[a][3]);
            float c = fg * g_c0[b * HH + jh] + ig * gg;
            g_c0[b * HH + jh] = c;
            hout[b * HH + jh] = og * tanhf(c);
        }
    } else {
        if (p < 1) return;
        const int nb  = bid - 64;                     // 0..127
        const int jpb = nb * 16;
        const float* __restrict__ A0 = g_h0[p & 1];         // h0[p-1]
        const float* __restrict__ A1 = g_h1[(p - 1) & 1];   // h1[p-2]
        const int i = tid & 63;           // batches 2i..2i+1
        const int j = tid >> 6;           // quad 4j..4j+3
        const int jh = (jpb >> 2) + j;

        float acc[2][4];
#pragma unroll
        for (int q = 0; q < 4; q++) {
            const float bv = bx1[q * HH + jh] + bh1[q * HH + jh];
            acc[0][q] = bv; acc[1][q] = bv;
        }
        for (int kc = 0; kc < 2 * HH; kc += 32) {
            const bool first = (kc < HH);
            const float* __restrict__ A = first ? A0 : A1;
            const float* __restrict__ W = first ? wx1 : wh1;
            const int kcol = first ? kc : kc - HH;
            __syncthreads();
#pragma unroll
            for (int r = 0; r < 4; r++) {
                const int s = tid + 256 * r;
                const int b = s >> 3, kq = s & 7;
                const float4 v = *(const float4*)&A[b * HH + kcol + kq * 4];
                As[kq*4+0][b] = v.x; As[kq*4+1][b] = v.y;
                As[kq*4+2][b] = v.z; As[kq*4+3][b] = v.w;
            }
            {
                const int row = tid >> 4, k2 = tid & 15;   // 16 rows
                const int jp = jpb + row;
                const int jo = (jp & 3) * HH + (jp >> 2);
                const float2 v = *(const float2*)&W[jo * HH + kcol + k2 * 2];
                Ws[k2*2+0][row] = v.x;
                Ws[k2*2+1][row] = v.y;
            }
            __syncthreads();
#pragma unroll
            for (int k = 0; k < 32; k++) {
                const float2 a = *(const float2*)&As[k][2 * i];
                const float4 w = *(const float4*)&Ws[k][4 * j];
                acc[0][0]+=a.x*w.x; acc[0][1]+=a.x*w.y; acc[0][2]+=a.x*w.z; acc[0][3]+=a.x*w.w;
                acc[1][0]+=a.y*w.x; acc[1][1]+=a.y*w.y; acc[1][2]+=a.y*w.z; acc[1][3]+=a.y*w.w;
            }
        }
        float* __restrict__ hout = g_h1[p & 1];
#pragma unroll
        for (int a = 0; a < 2; a++) {
            const int b = 2 * i + a;
            const float ig = sigf(acc[a][0]);
            const float fg = sigf(acc[a][1]);
            const float gg = tanhf(acc[a][2]);
            const float og = sigf(acc[a][3]);
            float c = fg * g_c1[b * HH + jh] + ig * gg;
            g_c1[b * HH + jh] = c;
            hout[b * HH + jh] = og * tanhf(c);
        }
    }
}

// FC head: one block per batch row, warp w computes hid unit w, warp 0 reduces.
__global__ __launch_bounds__(1024) void fc_kernel(
    const float* __restrict__ fc1_w, const float* __restrict__ fc1_b,
    const float* __restrict__ fc2_w, const float* __restrict__ fc2_b,
    float* __restrict__ out)
{
    __shared__ float hid[32];
    const int b = blockIdx.x;
    const int w = threadIdx.x >> 5, lane = threadIdx.x & 31;
    const float* __restrict__ h = g_h1[TT & 1] + b * HH;
    float s = 0.0f;
    for (int k = lane; k < HH; k += 32) s += h[k] * fc1_w[w * HH + k];
#pragma unroll
    for (int o = 16; o; o >>= 1) s += __shfl_xor_sync(0xFFFFFFFFu, s, o);
    if (lane == 0) hid[w] = fmaxf(s + fc1_b[w], 0.0f);
    __syncthreads();
    if (w == 0) {
        float v = hid[lane] * fc2_w[lane];
#pragma unroll
        for (int o = 16; o; o >>= 1) v += __shfl_xor_sync(0xFFFFFFFFu, v, o);
        if (lane == 0) out[b] = v + fc2_b[0];
    }
}

extern "C" void kernel_launch(void* const* d_in, const int* in_sizes, int n_in,
                              void* d_out, int out_size)
{
    const float* x      = (const float*)d_in[0];
    const float* proj_w = (const float*)d_in[1];
    const float* proj_b = (const float*)d_in[2];
    const float* wx0    = (const float*)d_in[3];
    const float* bx0    = (const float*)d_in[4];
    const float* wh0    = (const float*)d_in[5];
    const float* bh0    = (const float*)d_in[6];
    const float* wx1    = (const float*)d_in[7];
    const float* bx1    = (const float*)d_in[8];
    const float* wh1    = (const float*)d_in[9];
    const float* bh1    = (const float*)d_in[10];
    const float* fc1_w  = (const float*)d_in[11];
    const float* fc1_b  = (const float*)d_in[12];
    const float* fc2_w  = (const float*)d_in[13];
    const float* fc2_b  = (const float*)d_in[14];
    float* out = (float*)d_out;

    prep_M_kernel<<<GG, 256>>>(wx0, proj_w, proj_b, bx0, bh0);
    init_state_kernel<<<(BB * HH + 255) / 256, 256>>>();
    xg_kernel<<<1024 * 32, 256>>>(x);
    for (int p = 0; p <= TT; p++)
        phase_kernel<<<192, 256>>>(p, wh0, wx1, bx1, wh1, bh1);
    fc_kernel<<<BB, 1024>>>(fc1_w, fc1_b, fc2_w, fc2_b, out);
}

// round 16
// speedup vs baseline: 1.2077x; 1.2077x over previous
#include <cuda_runtime.h>
#include <cstdint>
#include <cstddef>

#define BB 128
#define TT 512
#define DD 256
#define HH 512
#define GG 2048  // 4*H
#define NBLK 128

// ---- device scratch (static globals: sanctioned no-alloc workaround) ----
__device__ float g_M[GG * DD];                 // permuted (wx0 @ proj_w)
__device__ float g_bias0[GG];                  // permuted wx0@proj_b + bx0 + bh0
__device__ float g_xg[(size_t)TT * BB * GG];   // x-gates, [t][b][jp] permuted
__device__ float g_h0[2][BB * HH];
__device__ float g_h1[2][BB * HH];
__device__ unsigned g_bar_arrive;
__device__ unsigned g_bar_epoch;

__device__ __forceinline__ float sigf(float x) { return 1.0f / (1.0f + __expf(-x)); }

// jo = (jp&3)*H + (jp>>2): row jp is gate quad (i,f,g,o) of hidden unit jp>>2
__global__ void prep_M_kernel(const float* __restrict__ wx0,
                              const float* __restrict__ proj_w,
                              const float* __restrict__ proj_b,
                              const float* __restrict__ bx0,
                              const float* __restrict__ bh0)
{
    const int jp = blockIdx.x;
    const int jo = (jp & 3) * HH + (jp >> 2);
    const int e  = threadIdx.x;
    float s = 0.0f;
    for (int d = 0; d < DD; d++) s += wx0[jo * DD + d] * proj_w[d * DD + e];
    g_M[jp * DD + e] = s;
    if (e == 0) {
        float bs = 0.0f;
        for (int d = 0; d < DD; d++) bs += wx0[jo * DD + d] * proj_b[d];
        g_bias0[jp] = bs + bx0[jo] + bh0[jo];
    }
}

__global__ void init_state_kernel()
{
    int i = blockIdx.x * blockDim.x + threadIdx.x;
    if (i < BB * HH) {
        g_h0[0][i] = 0.0f; g_h0[1][i] = 0.0f;
        g_h1[0][i] = 0.0f; g_h1[1][i] = 0.0f;
    }
    if (i == 0) { g_bar_arrive = 0; g_bar_epoch = 0; }
}

// xg[r][jp] = x_row(r) . g_M[jp] + g_bias0[jp], rows r = t*128 + b (t-major)
__global__ __launch_bounds__(256) void xg_kernel(const float* __restrict__ x)
{
    __shared__ float As[32][68];
    __shared__ float Bs[32][68];
    const int rb = blockIdx.x >> 5;
    const int cb = blockIdx.x & 31;
    const int tid = threadIdx.x;
    const int i = tid & 15;
    const int j = tid >> 4;
    const int colbase = cb * 64 + 4 * j;

    float acc[4][4];
#pragma unroll
    for (int q = 0; q < 4; q++) {
        const float bv = g_bias0[colbase + q];
        acc[0][q] = bv; acc[1][q] = bv; acc[2][q] = bv; acc[3][q] = bv;
    }
    for (int kc = 0; kc < DD; kc += 32) {
        __syncthreads();
#pragma unroll
        for (int r = 0; r < 2; r++) {
            const int s = tid + 256 * r;
            const int row = s >> 3, kq = s & 7;
            const int rout = rb * 64 + row;
            const int b = rout & 127, t = rout >> 7;
            const float4 v = *(const float4*)&x[((size_t)(b * TT + t)) * DD + kc + kq * 4];
            As[kq*4+0][row] = v.x; As[kq*4+1][row] = v.y;
            As[kq*4+2][row] = v.z; As[kq*4+3][row] = v.w;
        }
#pragma unroll
        for (int r = 0; r < 2; r++) {
            const int s = tid + 256 * r;
            const int row = s >> 3, kq = s & 7;
            const float4 v = *(const float4*)&g_M[(cb * 64 + row) * DD + kc + kq * 4];
            Bs[kq*4+0][row] = v.x; Bs[kq*4+1][row] = v.y;
            Bs[kq*4+2][row] = v.z; Bs[kq*4+3][row] = v.w;
        }
        __syncthreads();
#pragma unroll
        for (int k = 0; k < 32; k++) {
            const float4 a = *(const float4*)&As[k][4 * i];
            const float4 w = *(const float4*)&Bs[k][4 * j];
            acc[0][0]+=a.x*w.x; acc[0][1]+=a.x*w.y; acc[0][2]+=a.x*w.z; acc[0][3]+=a.x*w.w;
            acc[1][0]+=a.y*w.x; acc[1][1]+=a.y*w.y; acc[1][2]+=a.y*w.z; acc[1][3]+=a.y*w.w;
            acc[2][0]+=a.z*w.x; acc[2][1]+=a.z*w.y; acc[2][2]+=a.z*w.z; acc[2][3]+=a.z*w.w;
            acc[3][0]+=a.w*w.x; acc[3][1]+=a.w*w.y; acc[3][2]+=a.w*w.z; acc[3][3]+=a.w*w.w;
        }
    }
#pragma unroll
    for (int a = 0; a < 4; a++) {
        const int rout = rb * 64 + 4 * i + a;
        float4 v; v.x = acc[a][0]; v.y = acc[a][1]; v.z = acc[a][2]; v.w = acc[a][3];
        *(float4*)&g_xg[(size_t)rout * GG + colbase] = v;
    }
}

// ---------------------------------------------------------------------------
// Persistent skewed two-layer LSTM. 128 co-resident blocks, grid barrier per
// phase. Block bid owns layer0 cols [bid*16, bid*16+16) and layer1 cols
// [bid*16, bid*16+16); weights for both live in smem for the whole kernel;
// c-state lives in registers. h exchanged through L2 (__ldcg/__stcg).
// ---------------------------------------------------------------------------
__device__ __forceinline__ void grid_barrier(unsigned& epoch)
{
    __threadfence();          // publish this thread's h writes (device scope)
    __syncthreads();
    if (threadIdx.x == 0) {
        unsigned a = atomicAdd(&g_bar_arrive, 1u);
        if (a == NBLK - 1) {
            g_bar_arrive = 0;
            __threadfence();
            atomicExch(&g_bar_epoch, epoch + 1);
        } else {
            while (*((volatile unsigned*)&g_bar_epoch) <= epoch) { }
        }
    }
    epoch++;
    __syncthreads();
    __threadfence();          // acquire before reading peers' h
}

__global__ __launch_bounds__(256, 1) void lstm_persistent(
    const float* __restrict__ wh0,
    const float* __restrict__ wx1, const float* __restrict__ bx1,
    const float* __restrict__ wh1, const float* __restrict__ bh1)
{
    extern __shared__ float sm[];
    float* Ws0 = sm;                    // [512][16] wh0 rows (permuted)
    float* Ws1 = sm + 512 * 16;        // [512][16] wx1 rows
    float* Ws2 = sm + 2 * 512 * 16;    // [512][16] wh1 rows
    float* As  = sm + 3 * 512 * 16;    // [2][32][128] h staging (double buf)

    const int bid = blockIdx.x;
    const int tid = threadIdx.x;
    const int i   = tid & 63;           // batches 2i, 2i+1
    const int j   = tid >> 6;           // quad 0..3
    const int jh  = bid * 4 + j;        // hidden unit owned (both layers)
    const int colbase = bid * 16 + 4 * j;
    const int sb  = tid & 127;          // staging batch
    const int sk  = tid >> 7;           // staging k-phase (0/1)

    // ---- one-time weight preload into smem ----
    for (int u = tid; u < 2048; u += 256) {
        const int r  = u >> 7;          // local row 0..15
        const int k4 = u & 127;
        const int jp = bid * 16 + r;
        const int jo = (jp & 3) * HH + (jp >> 2);
        const float4 v0 = *(const float4*)&wh0[jo * HH + k4 * 4];
        const float4 v1 = *(const float4*)&wx1[jo * HH + k4 * 4];
        const float4 v2 = *(const float4*)&wh1[jo * HH + k4 * 4];
        Ws0[(k4*4+0)*16+r]=v0.x; Ws0[(k4*4+1)*16+r]=v0.y; Ws0[(k4*4+2)*16+r]=v0.z; Ws0[(k4*4+3)*16+r]=v0.w;
        Ws1[(k4*4+0)*16+r]=v1.x; Ws1[(k4*4+1)*16+r]=v1.y; Ws1[(k4*4+2)*16+r]=v1.z; Ws1[(k4*4+3)*16+r]=v1.w;
        Ws2[(k4*4+0)*16+r]=v2.x; Ws2[(k4*4+1)*16+r]=v2.y; Ws2[(k4*4+2)*16+r]=v2.z; Ws2[(k4*4+3)*16+r]=v2.w;
    }
    float bb1[4];
#pragma unroll
    for (int q = 0; q < 4; q++) bb1[q] = bx1[q * HH + jh] + bh1[q * HH + jh];
    float c0r[2] = {0.0f, 0.0f};
    float c1r[2] = {0.0f, 0.0f};
    unsigned epoch = 0;
    __syncthreads();

#pragma unroll 1
    for (int p = 0; p <= TT; p++) {
        const float* __restrict__ hA = g_h0[p & 1];        // h0 after step p-1
        const float* __restrict__ hB = g_h1[(p + 1) & 1];  // h1 after step p-2

        float acc0[2][4];
        float acc1[2][4];
#pragma unroll
        for (int q = 0; q < 4; q++) {
            acc0[0][q] = 0.0f; acc0[1][q] = 0.0f;
            acc1[0][q] = bb1[q]; acc1[1][q] = bb1[q];
        }
        if (p < TT) {
            const float* __restrict__ xg = g_xg + (size_t)p * BB * GG;
#pragma unroll
            for (int a = 0; a < 2; a++) {
                const float4 v = *(const float4*)&xg[(size_t)(2 * i + a) * GG + colbase];
                acc0[a][0] = v.x; acc0[a][1] = v.y; acc0[a][2] = v.z; acc0[a][3] = v.w;
            }
        }

        // ---- loop A: K over h0; layer0 (Ws0) + layer1-x (Ws1) ----
        float4 pre[4];
#pragma unroll
        for (int r = 0; r < 4; r++)
            pre[r] = __ldcg((const float4*)&hA[sb * HH + (sk + 2 * r) * 4]);
#pragma unroll 1
        for (int c = 0; c < 16; c++) {
            float* Ab = As + (c & 1) * (32 * 128);
#pragma unroll
            for (int r = 0; r < 4; r++) {
                const int kk = (sk + 2 * r) * 4;
                Ab[(kk+0)*128+sb] = pre[r].x; Ab[(kk+1)*128+sb] = pre[r].y;
                Ab[(kk+2)*128+sb] = pre[r].z; Ab[(kk+3)*128+sb] = pre[r].w;
            }
            __syncthreads();
            if (c < 15) {
                const int kc = (c + 1) * 32;
#pragma unroll
                for (int r = 0; r < 4; r++)
                    pre[r] = __ldcg((const float4*)&hA[sb * HH + kc + (sk + 2 * r) * 4]);
            }
            const float* __restrict__ W0 = Ws0 + (c * 32) * 16;
            const float* __restrict__ W1 = Ws1 + (c * 32) * 16;
#pragma unroll
            for (int k = 0; k < 32; k++) {
                const float2 a  = *(const float2*)&Ab[k * 128 + 2 * i];
                const float4 w0 = *(const float4*)&W0[k * 16 + 4 * j];
                const float4 w1 = *(const float4*)&W1[k * 16 + 4 * j];
                acc0[0][0]+=a.x*w0.x; acc0[0][1]+=a.x*w0.y; acc0[0][2]+=a.x*w0.z; acc0[0][3]+=a.x*w0.w;
                acc0[1][0]+=a.y*w0.x; acc0[1][1]+=a.y*w0.y; acc0[1][2]+=a.y*w0.z; acc0[1][3]+=a.y*w0.w;
                acc1[0][0]+=a.x*w1.x; acc1[0][1]+=a.x*w1.y; acc1[0][2]+=a.x*w1.z; acc1[0][3]+=a.x*w1.w;
                acc1[1][0]+=a.y*w1.x; acc1[1][1]+=a.y*w1.y; acc1[1][2]+=a.y*w1.z; acc1[1][3]+=a.y*w1.w;
            }
            __syncthreads();
        }

        // ---- loop B: K over h1; layer1-h (Ws2) ----
#pragma unroll
        for (int r = 0; r < 4; r++)
            pre[r] = __ldcg((const float4*)&hB[sb * HH + (sk + 2 * r) * 4]);
#pragma unroll 1
        for (int c = 0; c < 16; c++) {
            float* Ab = As + (c & 1) * (32 * 128);
#pragma unroll
            for (int r = 0; r < 4; r++) {
                const int kk = (sk + 2 * r) * 4;
                Ab[(kk+0)*128+sb] = pre[r].x; Ab[(kk+1)*128+sb] = pre[r].y;
                Ab[(kk+2)*128+sb] = pre[r].z; Ab[(kk+3)*128+sb] = pre[r].w;
            }
            __syncthreads();
            if (c < 15) {
                const int kc = (c + 1) * 32;
#pragma unroll
                for (int r = 0; r < 4; r++)
                    pre[r] = __ldcg((const float4*)&hB[sb * HH + kc + (sk + 2 * r) * 4]);
            }
            const float* __restrict__ W2 = Ws2 + (c * 32) * 16;
#pragma unroll
            for (int k = 0; k < 32; k++) {
                const float2 a  = *(const float2*)&Ab[k * 128 + 2 * i];
                const float4 w2 = *(const float4*)&W2[k * 16 + 4 * j];
                acc1[0][0]+=a.x*w2.x; acc1[0][1]+=a.x*w2.y; acc1[0][2]+=a.x*w2.z; acc1[0][3]+=a.x*w2.w;
                acc1[1][0]+=a.y*w2.x; acc1[1][1]+=a.y*w2.y; acc1[1][2]+=a.y*w2.z; acc1[1][3]+=a.y*w2.w;
            }
            __syncthreads();
        }

        // ---- epilogues (c-state in registers) ----
        if (p < TT) {
            float* __restrict__ hout = g_h0[(p + 1) & 1];
#pragma unroll
            for (int a = 0; a < 2; a++) {
                const int b = 2 * i + a;
                const float ig = sigf(acc0[a][0]);
                const float fg = sigf(acc0[a][1]);
                const float gg = tanhf(acc0[a][2]);
                const float og = sigf(acc0[a][3]);
                c0r[a] = fg * c0r[a] + ig * gg;
                __stcg(&hout[b * HH + jh], og * tanhf(c0r[a]));
            }
        }
        if (p >= 1) {
            float* __restrict__ hout = g_h1[p & 1];
#pragma unroll
            for (int a = 0; a < 2; a++) {
                const int b = 2 * i + a;
                const float ig = sigf(acc1[a][0]);
                const float fg = sigf(acc1[a][1]);
                const float gg = tanhf(acc1[a][2]);
                const float og = sigf(acc1[a][3]);
                c1r[a] = fg * c1r[a] + ig * gg;
                __stcg(&hout[b * HH + jh], og * tanhf(c1r[a]));
            }
        }

        grid_barrier(epoch);
    }
}

// FC head: one block per batch row, warp w computes hid unit w, warp 0 reduces.
__global__ __launch_bounds__(1024) void fc_kernel(
    const float* __restrict__ fc1_w, const float* __restrict__ fc1_b,
    const float* __restrict__ fc2_w, const float* __restrict__ fc2_b,
    float* __restrict__ out)
{
    __shared__ float hid[32];
    const int b = blockIdx.x;
    const int w = threadIdx.x >> 5, lane = threadIdx.x & 31;
    const float* __restrict__ h = g_h1[TT & 1] + b * HH;
    float s = 0.0f;
    for (int k = lane; k < HH; k += 32) s += h[k] * fc1_w[w * HH + k];
#pragma unroll
    for (int o = 16; o; o >>= 1) s += __shfl_xor_sync(0xFFFFFFFFu, s, o);
    if (lane == 0) hid[w] = fmaxf(s + fc1_b[w], 0.0f);
    __syncthreads();
    if (w == 0) {
        float v = hid[lane] * fc2_w[lane];
#pragma unroll
        for (int o = 16; o; o >>= 1) v += __shfl_xor_sync(0xFFFFFFFFu, v, o);
        if (lane == 0) out[b] = v + fc2_b[0];
    }
}

extern "C" void kernel_launch(void* const* d_in, const int* in_sizes, int n_in,
                              void* d_out, int out_size)
{
    const float* x      = (const float*)d_in[0];
    const float* proj_w = (const float*)d_in[1];
    const float* proj_b = (const float*)d_in[2];
    const float* wx0    = (const float*)d_in[3];
    const float* bx0    = (const float*)d_in[4];
    const float* wh0    = (const float*)d_in[5];
    const float* bh0    = (const float*)d_in[6];
    const float* wx1    = (const float*)d_in[7];
    const float* bx1    = (const float*)d_in[8];
    const float* wh1    = (const float*)d_in[9];
    const float* bh1    = (const float*)d_in[10];
    const float* fc1_w  = (const float*)d_in[11];
    const float* fc1_b  = (const float*)d_in[12];
    const float* fc2_w  = (const float*)d_in[13];
    const float* fc2_b  = (const float*)d_in[14];
    float* out = (float*)d_out;

    const int smem = (3 * 512 * 16 + 2 * 32 * 128) * (int)sizeof(float);  // 131072
    cudaFuncSetAttribute(lstm_persistent, cudaFuncAttributeMaxDynamicSharedMemorySize, smem);

    prep_M_kernel<<<GG, 256>>>(wx0, proj_w, proj_b, bx0, bh0);
    init_state_kernel<<<(BB * HH + 255) / 256, 256>>>();
    xg_kernel<<<1024 * 32, 256>>>(x);
    lstm_persistent<<<NBLK, 256, smem>>>(wh0, wx1, bx1, wh1, bh1);
    fc_kernel<<<BB, 1024>>>(fc1_w, fc1_b, fc2_w, fc2_b, out);
}